// round 12
// baseline (speedup 1.0000x reference)
#include <cuda_runtime.h>
#include <cstdint>

#define NN       512
#define NB       16
#define KTOP     50
#define NITERS   100
#define CL       8      // CTAs per cluster (one cluster per batch)
#define RPC      64     // sorted rows owned per CTA
#define NTHREADS 1024   // 32 warps, 2 rows per warp
#define CUT      30.0f  // block-skip threshold in log2 units
#define NARRIVE  (CL * (NTHREADS / 32))   // 256 producer-warp arrivals per barrier

__device__ __forceinline__ uint32_t smem_u32(const void* p) {
    return (uint32_t)__cvta_generic_to_shared(p);
}
__device__ __forceinline__ float ex2f_(float x) {
    float r; asm("ex2.approx.ftz.f32 %0, %1;" : "=f"(r) : "f"(x)); return r;
}
__device__ __forceinline__ float lg2f_(float x) {
    float r; asm("lg2.approx.f32 %0, %1;" : "=f"(r) : "f"(x)); return r;
}
// warp-max of a float via order-preserving u32 mapping + redux.sync.max.u32
__device__ __forceinline__ float warp_max_f32(float x) {
    int32_t b = __float_as_int(x);
    uint32_t u = (uint32_t)b ^ (uint32_t)((b >> 31) | 0x80000000);
    uint32_t r;
    asm("redux.sync.max.u32 %0, %1, 0xffffffff;" : "=r"(r) : "r"(u));
    uint32_t bb = r ^ ((~(uint32_t)((int32_t)r >> 31)) | 0x80000000u);
    return __int_as_float((int32_t)bb);
}
__device__ __forceinline__ void cluster_sync_() {
    asm volatile("barrier.cluster.arrive.aligned;" ::: "memory");
    asm volatile("barrier.cluster.wait.aligned;" ::: "memory");
}
__device__ __forceinline__ uint32_t ctarank_() {
    uint32_t r; asm("mov.u32 %0, %%cluster_ctarank;" : "=r"(r)); return r;
}
__device__ __forceinline__ void st_cluster_f32(uint32_t laddr, uint32_t rank, float v) {
    asm volatile(
        "{\n\t.reg .b32 ra;\n\t"
        "mapa.shared::cluster.u32 ra, %0, %1;\n\t"
        "st.shared::cluster.f32 [ra], %2;\n\t}"
        :: "r"(laddr), "r"(rank), "f"(v) : "memory");
}
// Arrive (release, cluster scope) on the mbarrier at local offset `laddr`
// inside cluster CTA `rank`. Orders this thread's prior DSMEM stores.
__device__ __forceinline__ void mbar_arrive_cluster(uint32_t laddr, uint32_t rank) {
    asm volatile(
        "{\n\t.reg .b32 ra;\n\t"
        "mapa.shared::cluster.u32 ra, %0, %1;\n\t"
        "mbarrier.arrive.release.cluster.shared::cluster.b64 _, [ra];\n\t}"
        :: "r"(laddr), "r"(rank) : "memory");
}
// Wait (acquire, cluster scope) on local mbarrier for phase `parity`.
__device__ __forceinline__ void mbar_wait_cluster(uint32_t addr, uint32_t parity) {
    uint32_t done;
    asm volatile(
        "{\n\t.reg .pred p;\n\t"
        "mbarrier.try_wait.parity.acquire.cluster.shared::cta.b64 p, [%1], %2;\n\t"
        "selp.b32 %0, 1, 0, p;\n\t}"
        : "=r"(done) : "r"(addr), "r"(parity) : "memory");
    if (!done) {
        asm volatile(
            "{\n\t.reg .pred P1;\n\t"
            "WL_%=:\n\t"
            "mbarrier.try_wait.parity.acquire.cluster.shared::cta.b64 P1, [%0], %1, 0x989680;\n\t"
            "@P1 bra.uni WD_%=;\n\t"
            "bra.uni WL_%=;\n\t"
            "WD_%=:\n\t}"
            :: "r"(addr), "r"(parity) : "memory");
    }
}

// One half-step in sorted space: each warp owns 2 rows (one interleaved pair):
//   dst[a] = -lse2_b( M[a,b] + W[b] )
// Pass 1: exact row max over all 512 cols (W register-resident).
// Pass 2: exp-sum over 128-col blocks surviving the CUT, predicated unrolled.
// After the DSMEM stores, lane<CL arrives on the destination-ready mbarrier
// (same local offset `barl`) in every cluster CTA.
__device__ __forceinline__ void half_step(
    const float* __restrict__ Msh, const float* __restrict__ Wsh,
    uint32_t dstb, uint32_t barl, int rowbase, int gbase, int lane)
{
    const float4* W4 = (const float4*)Wsh;
    float w[16];
#pragma unroll
    for (int q = 0; q < 4; q++) {
        float4 t = W4[32 * q + lane];
        w[4*q+0] = t.x; w[4*q+1] = t.y; w[4*q+2] = t.z; w[4*q+3] = t.w;
    }

    const float4* M0 = (const float4*)(Msh + (size_t)rowbase * NN);
    const float4* M1 = (const float4*)(Msh + (size_t)(rowbase + 1) * NN);

    // pass 1: per-block lane maxes of x = M + w
    float mq0[4], mq1[4];
#pragma unroll
    for (int q = 0; q < 4; q++) {
        float4 a = M0[32 * q + lane];
        float4 b = M1[32 * q + lane];
        float a0 = a.x + w[4*q+0], a1 = a.y + w[4*q+1];
        float a2 = a.z + w[4*q+2], a3 = a.w + w[4*q+3];
        float b0 = b.x + w[4*q+0], b1 = b.y + w[4*q+1];
        float b2 = b.z + w[4*q+2], b3 = b.w + w[4*q+3];
        mq0[q] = fmaxf(fmaxf(a0, a1), fmaxf(a2, a3));
        mq1[q] = fmaxf(fmaxf(b0, b1), fmaxf(b2, b3));
    }
    const float m0 = warp_max_f32(fmaxf(fmaxf(mq0[0], mq0[1]), fmaxf(mq0[2], mq0[3])));
    const float m1 = warp_max_f32(fmaxf(fmaxf(mq1[0], mq1[1]), fmaxf(mq1[2], mq1[3])));
    const float c0 = m0 - CUT, c1 = m1 - CUT;

    // active-block mask (warp-uniform); both rows of the pair share it
    unsigned mask = 0;
#pragma unroll
    for (int q = 0; q < 4; q++)
        if (__any_sync(0xffffffffu, (mq0[q] > c0) || (mq1[q] > c1)))
            mask |= 1u << q;

    // pass 2: exp-sum over active blocks (predicated unroll, w in registers)
    float s0a = 0.f, s0b = 0.f, s0c = 0.f, s0d = 0.f;
    float s1a = 0.f, s1b = 0.f, s1c = 0.f, s1d = 0.f;
#pragma unroll
    for (int q = 0; q < 4; q++) {
        if (mask & (1u << q)) {
            float4 a = M0[32 * q + lane];
            float4 b = M1[32 * q + lane];
            s0a += ex2f_((a.x + w[4*q+0]) - m0);
            s0b += ex2f_((a.y + w[4*q+1]) - m0);
            s0c += ex2f_((a.z + w[4*q+2]) - m0);
            s0d += ex2f_((a.w + w[4*q+3]) - m0);
            s1a += ex2f_((b.x + w[4*q+0]) - m1);
            s1b += ex2f_((b.y + w[4*q+1]) - m1);
            s1c += ex2f_((b.z + w[4*q+2]) - m1);
            s1d += ex2f_((b.w + w[4*q+3]) - m1);
        }
    }
    float sum0 = (s0a + s0b) + (s0c + s0d);
    float sum1 = (s1a + s1b) + (s1c + s1d);
#pragma unroll
    for (int o = 16; o > 0; o >>= 1) {
        sum0 += __shfl_xor_sync(0xffffffffu, sum0, o);
        sum1 += __shfl_xor_sync(0xffffffffu, sum1, o);
    }
    const float v0 = -(m0 + lg2f_(sum0));
    const float v1 = -(m1 + lg2f_(sum1));
    if (lane < CL) {
        st_cluster_f32(dstb + (uint32_t)(gbase)     * 4u, (uint32_t)lane, v0);
        st_cluster_f32(dstb + (uint32_t)(gbase + 1) * 4u, (uint32_t)lane, v1);
        mbar_arrive_cluster(barl, (uint32_t)lane);
    }
}

// Sorted coordinate space: t = sort_desc(s), p: sorted pos -> original idx.
// M[a,b] = nk2*(t_a - t_b)^2 (symmetric, band-dominant).
//   step 1:  V[a] = -lse2_b( M[a,b] + U[b] )    (ready when vbar phase `it` completes)
//   step 2:  U[a] = -lse2_b( M[a,b] + V[b] )    (ready when ubar phase `it` completes)
// Race-freedom: V(it+1) producers first wait ubar(it), whose 256 arrivals each
// happen only after that producer warp finished reading V(it).
__global__ void __launch_bounds__(NTHREADS, 1) __cluster_dims__(CL, 1, 1)
sinkhorn_topk_kernel(const float* __restrict__ scores, float* __restrict__ out)
{
    extern __shared__ float Msh[];                 // [RPC][NN] = 128 KB
    __shared__ __align__(16) float t_sh[NN];       // sorted descending
    __shared__ __align__(16) float U_sh[NN];       // row potentials (sorted space)
    __shared__ __align__(16) float V_sh[NN];       // col potentials (sorted space)
    __shared__ int p_sh[NN];                       // sorted pos -> original index
    __shared__ __align__(8) uint64_t vbar_sh, ubar_sh;

    const int tid   = threadIdx.x;
    const int lane  = tid & 31;
    const int warp  = tid >> 5;
    const int rank  = (int)ctarank_();
    const int batch = blockIdx.x / CL;
    const float nk2 = -1442.6950408889634f;        // -log2(e)/EPSILON

    const uint32_t vbarl = smem_u32(&vbar_sh);
    const uint32_t ubarl = smem_u32(&ubar_sh);

    if (tid == 0) {
        asm volatile("mbarrier.init.shared.b64 [%0], %1;" :: "r"(vbarl), "r"(NARRIVE) : "memory");
        asm volatile("mbarrier.init.shared.b64 [%0], %1;" :: "r"(ubarl), "r"(NARRIVE) : "memory");
    }
    if (tid < NN) {
        t_sh[tid] = scores[batch * NN + tid];
        p_sh[tid] = tid;
        U_sh[tid] = 0.0f;
        V_sh[tid] = 0.0f;
    }
    __syncthreads();

    // Bitonic sort (value, index) descending — threads 0..511 active
    for (int k = 2; k <= NN; k <<= 1) {
        for (int j = k >> 1; j > 0; j >>= 1) {
            if (tid < NN) {
                int ixj = tid ^ j;
                if (ixj > tid) {
                    float a = t_sh[tid], b = t_sh[ixj];
                    bool desc = ((tid & k) == 0);
                    if (desc ? (a < b) : (a > b)) {
                        t_sh[tid] = b; t_sh[ixj] = a;
                        int pa = p_sh[tid]; p_sh[tid] = p_sh[ixj]; p_sh[ixj] = pa;
                    }
                }
            }
            __syncthreads();
        }
    }

    // Build this CTA's 64 sorted-space rows of M (iteration-invariant)
    {
        const int abase = rank * RPC;
        const int col = tid & (NN - 1);          // 0..511
        const int c0  = (tid >> 9) * (RPC / 2);  // rows 0..31 / 32..63
        const float te = t_sh[col];
#pragma unroll 4
        for (int c = c0; c < c0 + RPC / 2; c++) {
            float d = t_sh[abase + c] - te;
            Msh[c * NN + col] = (d * nk2) * d;
        }
    }
    __syncthreads();
    cluster_sync_();   // all CTAs' U/V init + mbarrier init visible cluster-wide

    const uint32_t Ub = smem_u32(U_sh);
    const uint32_t Vb = smem_u32(V_sh);
    const int rowbase = warp * 2;              // 2 rows per warp
    const int gbase   = rank * RPC + rowbase;  // global sorted row index

    for (int it = 0; it < NITERS; it++) {
        if (it > 0) mbar_wait_cluster(ubarl, (uint32_t)((it - 1) & 1)); // U(it-1) ready
        half_step(Msh, U_sh, Vb, vbarl, rowbase, gbase, lane);          // -> V(it)
        mbar_wait_cluster(vbarl, (uint32_t)(it & 1));                   // V(it) ready
        half_step(Msh, V_sh, Ub, ubarl, rowbase, gbase, lane);          // -> U(it)
    }
    mbar_wait_cluster(ubarl, (uint32_t)((NITERS - 1) & 1));             // final U ready

    // out[p[a]] = sum_{j<K} 2^( nk2*(t_a - t_j)^2 + U[a] + V[j] )
#pragma unroll
    for (int c = 0; c < 2; c++) {
        const int a = gbase + c;
        const float ta = t_sh[a];
        const float ua = U_sh[a];
        float acc = 0.0f;
        for (int jj = lane; jj < KTOP; jj += 32) {
            float d = ta - t_sh[jj];
            acc += ex2f_(fmaf(d * nk2, d, ua + V_sh[jj]));
        }
#pragma unroll
        for (int o = 16; o > 0; o >>= 1)
            acc += __shfl_xor_sync(0xffffffffu, acc, o);
        if (lane == 0) out[batch * NN + p_sh[a]] = acc;
    }

    // no CTA may exit while peers could still store into its SMEM
    __syncthreads();
    cluster_sync_();
}

extern "C" void kernel_launch(void* const* d_in, const int* in_sizes, int n_in,
                              void* d_out, int out_size) {
    const float* scores = (const float*)d_in[0];
    float* outp = (float*)d_out;
    cudaFuncSetAttribute(sinkhorn_topk_kernel,
                         cudaFuncAttributeMaxDynamicSharedMemorySize,
                         RPC * NN * (int)sizeof(float));
    sinkhorn_topk_kernel<<<NB * CL, NTHREADS, RPC * NN * sizeof(float)>>>(scores, outp);
}

// round 13
// speedup vs baseline: 1.1221x; 1.1221x over previous
#include <cuda_runtime.h>
#include <cstdint>

#define NN       512
#define NB       16
#define KTOP     50
#define NITERS   100
#define CL       8      // CTAs per cluster (one cluster per batch)
#define RPC      64     // sorted rows owned per CTA
#define NTHREADS 1024   // 32 warps, 2 rows per warp
#define CUT      30.0f  // block-skip threshold in log2 units
#define CHECK    10     // convergence check period (iterations)
#define TOL      1e-5f  // freeze detection threshold (log2 units)

__device__ __forceinline__ uint32_t smem_u32(const void* p) {
    return (uint32_t)__cvta_generic_to_shared(p);
}
__device__ __forceinline__ float ex2f_(float x) {
    float r; asm("ex2.approx.ftz.f32 %0, %1;" : "=f"(r) : "f"(x)); return r;
}
__device__ __forceinline__ float lg2f_(float x) {
    float r; asm("lg2.approx.f32 %0, %1;" : "=f"(r) : "f"(x)); return r;
}
// warp-max of a float via order-preserving u32 mapping + redux.sync.max.u32
__device__ __forceinline__ float warp_max_f32(float x) {
    int32_t b = __float_as_int(x);
    uint32_t u = (uint32_t)b ^ (uint32_t)((b >> 31) | 0x80000000);
    uint32_t r;
    asm("redux.sync.max.u32 %0, %1, 0xffffffff;" : "=r"(r) : "r"(u));
    uint32_t bb = r ^ ((~(uint32_t)((int32_t)r >> 31)) | 0x80000000u);
    return __int_as_float((int32_t)bb);
}
__device__ __forceinline__ void cluster_sync_() {
    asm volatile("barrier.cluster.arrive.aligned;" ::: "memory");
    asm volatile("barrier.cluster.wait.aligned;" ::: "memory");
}
__device__ __forceinline__ uint32_t ctarank_() {
    uint32_t r; asm("mov.u32 %0, %%cluster_ctarank;" : "=r"(r)); return r;
}
__device__ __forceinline__ void st_cluster_f32(uint32_t laddr, uint32_t rank, float v) {
    asm volatile(
        "{\n\t.reg .b32 ra;\n\t"
        "mapa.shared::cluster.u32 ra, %0, %1;\n\t"
        "st.shared::cluster.f32 [ra], %2;\n\t}"
        :: "r"(laddr), "r"(rank), "f"(v) : "memory");
}
__device__ __forceinline__ void st_cluster_u32(uint32_t laddr, uint32_t rank, uint32_t v) {
    asm volatile(
        "{\n\t.reg .b32 ra;\n\t"
        "mapa.shared::cluster.u32 ra, %0, %1;\n\t"
        "st.shared::cluster.u32 [ra], %2;\n\t}"
        :: "r"(laddr), "r"(rank), "r"(v) : "memory");
}

// One half-step in sorted space: each warp owns 2 rows (one interleaved pair):
//   dst[a] = -lse2_b( M[a,b] + W[b] )
// Pass 1: exact row max over all 512 cols (W register-resident).
// Pass 2: exp-sum over 128-col blocks surviving the CUT, predicated unrolled.
// Returns the two computed potentials (warp-uniform) via o0/o1.
__device__ __forceinline__ void half_step(
    const float* __restrict__ Msh, const float* __restrict__ Wsh,
    uint32_t dstb, int rowbase, int gbase, int lane,
    float* o0, float* o1)
{
    const float4* W4 = (const float4*)Wsh;
    float w[16];
#pragma unroll
    for (int q = 0; q < 4; q++) {
        float4 t = W4[32 * q + lane];
        w[4*q+0] = t.x; w[4*q+1] = t.y; w[4*q+2] = t.z; w[4*q+3] = t.w;
    }

    const float4* M0 = (const float4*)(Msh + (size_t)rowbase * NN);
    const float4* M1 = (const float4*)(Msh + (size_t)(rowbase + 1) * NN);

    // pass 1: per-block lane maxes of x = M + w
    float mq0[4], mq1[4];
#pragma unroll
    for (int q = 0; q < 4; q++) {
        float4 a = M0[32 * q + lane];
        float4 b = M1[32 * q + lane];
        float a0 = a.x + w[4*q+0], a1 = a.y + w[4*q+1];
        float a2 = a.z + w[4*q+2], a3 = a.w + w[4*q+3];
        float b0 = b.x + w[4*q+0], b1 = b.y + w[4*q+1];
        float b2 = b.z + w[4*q+2], b3 = b.w + w[4*q+3];
        mq0[q] = fmaxf(fmaxf(a0, a1), fmaxf(a2, a3));
        mq1[q] = fmaxf(fmaxf(b0, b1), fmaxf(b2, b3));
    }
    const float m0 = warp_max_f32(fmaxf(fmaxf(mq0[0], mq0[1]), fmaxf(mq0[2], mq0[3])));
    const float m1 = warp_max_f32(fmaxf(fmaxf(mq1[0], mq1[1]), fmaxf(mq1[2], mq1[3])));
    const float c0 = m0 - CUT, c1 = m1 - CUT;

    // active-block mask (warp-uniform); both rows of the pair share it
    unsigned mask = 0;
#pragma unroll
    for (int q = 0; q < 4; q++)
        if (__any_sync(0xffffffffu, (mq0[q] > c0) || (mq1[q] > c1)))
            mask |= 1u << q;

    // pass 2: exp-sum over active blocks (predicated unroll, w in registers)
    float s0a = 0.f, s0b = 0.f, s0c = 0.f, s0d = 0.f;
    float s1a = 0.f, s1b = 0.f, s1c = 0.f, s1d = 0.f;
#pragma unroll
    for (int q = 0; q < 4; q++) {
        if (mask & (1u << q)) {
            float4 a = M0[32 * q + lane];
            float4 b = M1[32 * q + lane];
            s0a += ex2f_((a.x + w[4*q+0]) - m0);
            s0b += ex2f_((a.y + w[4*q+1]) - m0);
            s0c += ex2f_((a.z + w[4*q+2]) - m0);
            s0d += ex2f_((a.w + w[4*q+3]) - m0);
            s1a += ex2f_((b.x + w[4*q+0]) - m1);
            s1b += ex2f_((b.y + w[4*q+1]) - m1);
            s1c += ex2f_((b.z + w[4*q+2]) - m1);
            s1d += ex2f_((b.w + w[4*q+3]) - m1);
        }
    }
    float sum0 = (s0a + s0b) + (s0c + s0d);
    float sum1 = (s1a + s1b) + (s1c + s1d);
#pragma unroll
    for (int o = 16; o > 0; o >>= 1) {
        sum0 += __shfl_xor_sync(0xffffffffu, sum0, o);
        sum1 += __shfl_xor_sync(0xffffffffu, sum1, o);
    }
    const float v0 = -(m0 + lg2f_(sum0));
    const float v1 = -(m1 + lg2f_(sum1));
    if (lane < CL) {
        st_cluster_f32(dstb + (uint32_t)(gbase)     * 4u, (uint32_t)lane, v0);
        st_cluster_f32(dstb + (uint32_t)(gbase + 1) * 4u, (uint32_t)lane, v1);
    }
    *o0 = v0;
    *o1 = v1;
}

// Sorted coordinate space: t = sort_desc(s), p: sorted pos -> original idx.
// M[a,b] = nk2*(t_a - t_b)^2 (symmetric, band-dominant).
//   step 1:  V[a] = -lse2_b( M[a,b] + U[b] )
//   step 2:  U[a] = -lse2_b( M[a,b] + V[b] )
// Early exit: every CHECK iters, if NO warp cluster-wide saw |dU| > TOL over the
// window, the fixed point is frozen in fp32 and remaining iterations are no-ops.
// out[p[a]] = sum_{j<K} 2^( M[a,j] + U[a] + V[j] )
__global__ void __launch_bounds__(NTHREADS, 1) __cluster_dims__(CL, 1, 1)
sinkhorn_topk_kernel(const float* __restrict__ scores, float* __restrict__ out)
{
    extern __shared__ float Msh[];                 // [RPC][NN] = 128 KB
    __shared__ __align__(16) float t_sh[NN];       // sorted descending
    __shared__ __align__(16) float U_sh[NN];       // row potentials (sorted space)
    __shared__ __align__(16) float V_sh[NN];       // col potentials (sorted space)
    __shared__ int p_sh[NN];                       // sorted pos -> original index
    __shared__ int flag_sh;                        // nonconvergence flag

    const int tid   = threadIdx.x;
    const int lane  = tid & 31;
    const int warp  = tid >> 5;
    const int rank  = (int)ctarank_();
    const int batch = blockIdx.x / CL;
    const float nk2 = -1442.6950408889634f;        // -log2(e)/EPSILON

    if (tid < NN) {
        t_sh[tid] = scores[batch * NN + tid];
        p_sh[tid] = tid;
        U_sh[tid] = 0.0f;
        V_sh[tid] = 0.0f;
    }
    if (tid == 0) flag_sh = 1;
    __syncthreads();

    // Bitonic sort (value, index) descending — threads 0..511 active
    for (int k = 2; k <= NN; k <<= 1) {
        for (int j = k >> 1; j > 0; j >>= 1) {
            if (tid < NN) {
                int ixj = tid ^ j;
                if (ixj > tid) {
                    float a = t_sh[tid], b = t_sh[ixj];
                    bool desc = ((tid & k) == 0);
                    if (desc ? (a < b) : (a > b)) {
                        t_sh[tid] = b; t_sh[ixj] = a;
                        int pa = p_sh[tid]; p_sh[tid] = p_sh[ixj]; p_sh[ixj] = pa;
                    }
                }
            }
            __syncthreads();
        }
    }

    // Build this CTA's 64 sorted-space rows of M (iteration-invariant)
    {
        const int abase = rank * RPC;
        const int col = tid & (NN - 1);          // 0..511
        const int c0  = (tid >> 9) * (RPC / 2);  // rows 0..31 / 32..63
        const float te = t_sh[col];
#pragma unroll 4
        for (int c = c0; c < c0 + RPC / 2; c++) {
            float d = t_sh[abase + c] - te;
            Msh[c * NN + col] = (d * nk2) * d;
        }
    }
    __syncthreads();
    cluster_sync_();   // all CTAs' U/V init + M done before any peer stores arrive

    const uint32_t Ub = smem_u32(U_sh);
    const uint32_t Vb = smem_u32(V_sh);
    const uint32_t Fb = smem_u32(&flag_sh);
    const int rowbase = warp * 2;              // 2 rows per warp
    const int gbase   = rank * RPC + rowbase;  // global sorted row index

    float u0p = 0.0f, u1p = 0.0f;              // this warp's U at last check
    float d0, d1, u0, u1;

    for (int it = 0; it < NITERS; it++) {
        const bool chk = ((it % CHECK) == (CHECK - 1));
        // reset flag: ordered before any peer flag-store (2 cluster syncs away)
        if (chk && tid == 0) flag_sh = 0;

        half_step(Msh, U_sh, Vb, rowbase, gbase, lane, &d0, &d1);   // -> V
        cluster_sync_();
        half_step(Msh, V_sh, Ub, rowbase, gbase, lane, &u0, &u1);   // -> U
        cluster_sync_();

        if (chk) {
            const float delta = fmaxf(fabsf(u0 - u0p), fabsf(u1 - u1p));
            u0p = u0; u1p = u1;
            if (lane == 0 && delta > TOL) flag_sh = 1;   // benign race (all write 1)
            __syncthreads();
            const int f = flag_sh;
            if (f && tid < CL) st_cluster_u32(Fb, (uint32_t)tid, 1u);
            cluster_sync_();                             // flag propagation
            if (flag_sh == 0) break;                     // uniform cluster-wide
        }
    }

    // out[p[a]] = sum_{j<K} 2^( nk2*(t_a - t_j)^2 + U[a] + V[j] )
#pragma unroll
    for (int c = 0; c < 2; c++) {
        const int a = gbase + c;
        const float ta = t_sh[a];
        const float ua = U_sh[a];
        float acc = 0.0f;
        for (int jj = lane; jj < KTOP; jj += 32) {
            float d = ta - t_sh[jj];
            acc += ex2f_(fmaf(d * nk2, d, ua + V_sh[jj]));
        }
#pragma unroll
        for (int o = 16; o > 0; o >>= 1)
            acc += __shfl_xor_sync(0xffffffffu, acc, o);
        if (lane == 0) out[batch * NN + p_sh[a]] = acc;
    }

    // no CTA may exit while peers could still store into its SMEM
    __syncthreads();
    cluster_sync_();
}

extern "C" void kernel_launch(void* const* d_in, const int* in_sizes, int n_in,
                              void* d_out, int out_size) {
    const float* scores = (const float*)d_in[0];
    float* outp = (float*)d_out;
    cudaFuncSetAttribute(sinkhorn_topk_kernel,
                         cudaFuncAttributeMaxDynamicSharedMemorySize,
                         RPC * NN * (int)sizeof(float));
    sinkhorn_topk_kernel<<<NB * CL, NTHREADS, RPC * NN * sizeof(float)>>>(scores, outp);
}

// round 14
// speedup vs baseline: 1.5137x; 1.3490x over previous
#include <cuda_runtime.h>
#include <cstdint>

#define NN       512
#define NB       16
#define KTOP     50
#define NITERS   100
#define CL       8      // CTAs per cluster (one cluster per batch)
#define RPC      64     // sorted rows owned per CTA
#define NTHREADS 1024   // 32 warps, 2 rows per warp
#define NCHUNK   16     // 32-wide column chunks
#define CUT      30.0f  // chunk-skip threshold in log2 units

__device__ __forceinline__ uint32_t smem_u32(const void* p) {
    return (uint32_t)__cvta_generic_to_shared(p);
}
__device__ __forceinline__ float ex2f_(float x) {
    float r; asm("ex2.approx.ftz.f32 %0, %1;" : "=f"(r) : "f"(x)); return r;
}
__device__ __forceinline__ float lg2f_(float x) {
    float r; asm("lg2.approx.f32 %0, %1;" : "=f"(r) : "f"(x)); return r;
}
// warp-max of a float via order-preserving u32 mapping + redux.sync.max.u32
__device__ __forceinline__ float warp_max_f32(float x) {
    int32_t b = __float_as_int(x);
    uint32_t u = (uint32_t)b ^ (uint32_t)((b >> 31) | 0x80000000);
    uint32_t r;
    asm("redux.sync.max.u32 %0, %1, 0xffffffff;" : "=r"(r) : "r"(u));
    uint32_t bb = r ^ ((~(uint32_t)((int32_t)r >> 31)) | 0x80000000u);
    return __int_as_float((int32_t)bb);
}
__device__ __forceinline__ void cluster_sync_() {
    asm volatile("barrier.cluster.arrive.aligned;" ::: "memory");
    asm volatile("barrier.cluster.wait.aligned;" ::: "memory");
}
__device__ __forceinline__ uint32_t ctarank_() {
    uint32_t r; asm("mov.u32 %0, %%cluster_ctarank;" : "=r"(r)); return r;
}
__device__ __forceinline__ void st_cluster_f32(uint32_t laddr, uint32_t rank, float v) {
    asm volatile(
        "{\n\t.reg .b32 ra;\n\t"
        "mapa.shared::cluster.u32 ra, %0, %1;\n\t"
        "st.shared::cluster.f32 [ra], %2;\n\t}"
        :: "r"(laddr), "r"(rank), "f"(v) : "memory");
}

// One half-step in sorted space: each warp owns 2 rows.
//   dst[a] = -lse2_b( M[a,b] + W[b] ),  shift = W[a]  (diag term M[a,a]=0 => sum >= 1)
// Chunk-skip: keep 32-col chunk q iff Mmax[a][q] + Wmax > W[a] - CUT
// (skipped elements each < 2^(W[a]-CUT), bound via precomputed Mmax and global Wmax).
__device__ __forceinline__ void half_step(
    const float* __restrict__ Msh, const float* __restrict__ Wsh,
    const float* __restrict__ Mmax,
    uint32_t dstb, int rowbase, int gbase, int lane)
{
    // global max of W (all 512), for the skip bound
    const float4* W4 = (const float4*)Wsh;
    float wm = -3.402823466e38f;
#pragma unroll
    for (int q = 0; q < 4; q++) {
        float4 t = W4[32 * q + lane];
        wm = fmaxf(wm, fmaxf(fmaxf(t.x, t.y), fmaxf(t.z, t.w)));
    }
    wm = warp_max_f32(wm);

    const float wa0 = Wsh[gbase];
    const float wa1 = Wsh[gbase + 1];
    const float thr0 = wa0 - CUT - wm;
    const float thr1 = wa1 - CUT - wm;

    // chunk masks via one ballot per row (lane q tests chunk q; q<16)
    const int q16 = lane & 15;
    const float mm0 = Mmax[rowbase * NCHUNK + q16];
    const float mm1 = Mmax[(rowbase + 1) * NCHUNK + q16];
    unsigned mask = (__ballot_sync(0xffffffffu, mm0 > thr0) |
                     __ballot_sync(0xffffffffu, mm1 > thr1)) & 0xFFFFu;

    const float* M0 = Msh + (size_t)rowbase * NN;
    const float* M1 = M0 + NN;

    float s0 = 0.0f, s1 = 0.0f;
    while (mask) {
        const int q = __ffs(mask) - 1;
        mask &= mask - 1;
        const int idx = 32 * q + lane;
        const float wb = Wsh[idx];
        s0 += ex2f_(M0[idx] + (wb - wa0));
        s1 += ex2f_(M1[idx] + (wb - wa1));
    }
#pragma unroll
    for (int o = 16; o > 0; o >>= 1) {
        s0 += __shfl_xor_sync(0xffffffffu, s0, o);
        s1 += __shfl_xor_sync(0xffffffffu, s1, o);
    }
    const float v0 = -(wa0 + lg2f_(s0));
    const float v1 = -(wa1 + lg2f_(s1));
    if (lane < CL) {
        st_cluster_f32(dstb + (uint32_t)(gbase)     * 4u, (uint32_t)lane, v0);
        st_cluster_f32(dstb + (uint32_t)(gbase + 1) * 4u, (uint32_t)lane, v1);
    }
}

// Sorted coordinate space: t = sort_desc(s), p: sorted pos -> original idx.
// M[a,b] = nk2*(t_a - t_b)^2 (symmetric, band-dominant).
//   step 1:  V[a] = -lse2_b( M[a,b] + U[b] )
//   step 2:  U[a] = -lse2_b( M[a,b] + V[b] )
// out[p[a]] = sum_{j<K} 2^( M[a,j] + U[a] + V[j] )
__global__ void __launch_bounds__(NTHREADS, 1) __cluster_dims__(CL, 1, 1)
sinkhorn_topk_kernel(const float* __restrict__ scores, float* __restrict__ out)
{
    extern __shared__ float Msh[];                 // [RPC][NN] = 128 KB
    __shared__ __align__(16) float t_sh[NN];       // sorted descending
    __shared__ __align__(16) float U_sh[NN];       // row potentials (sorted space)
    __shared__ __align__(16) float V_sh[NN];       // col potentials (sorted space)
    __shared__ __align__(16) float Mmax_sh[RPC * NCHUNK];  // per-(row,chunk) max of M
    __shared__ int p_sh[NN];                       // sorted pos -> original index

    const int tid   = threadIdx.x;
    const int lane  = tid & 31;
    const int warp  = tid >> 5;
    const int rank  = (int)ctarank_();
    const int batch = blockIdx.x / CL;
    const float nk2 = -1442.6950408889634f;        // -log2(e)/EPSILON

    if (tid < NN) {
        t_sh[tid] = scores[batch * NN + tid];
        p_sh[tid] = tid;
        U_sh[tid] = 0.0f;
        V_sh[tid] = 0.0f;
    }
    __syncthreads();

    // Bitonic sort (value, index) descending — threads 0..511 active
    for (int k = 2; k <= NN; k <<= 1) {
        for (int j = k >> 1; j > 0; j >>= 1) {
            if (tid < NN) {
                int ixj = tid ^ j;
                if (ixj > tid) {
                    float a = t_sh[tid], b = t_sh[ixj];
                    bool desc = ((tid & k) == 0);
                    if (desc ? (a < b) : (a > b)) {
                        t_sh[tid] = b; t_sh[ixj] = a;
                        int pa = p_sh[tid]; p_sh[tid] = p_sh[ixj]; p_sh[ixj] = pa;
                    }
                }
            }
            __syncthreads();
        }
    }

    // Build this CTA's 64 sorted-space rows of M (iteration-invariant)
    {
        const int abase = rank * RPC;
        const int col = tid & (NN - 1);          // 0..511
        const int c0  = (tid >> 9) * (RPC / 2);  // rows 0..31 / 32..63
        const float te = t_sh[col];
#pragma unroll 4
        for (int c = c0; c < c0 + RPC / 2; c++) {
            float d = t_sh[abase + c] - te;
            Msh[c * NN + col] = (d * nk2) * d;
        }
    }
    __syncthreads();

    // Per-(row,chunk) maxima of M: thread -> (row = tid>>4, chunk = tid&15)
    {
        const int r = tid >> 4;
        const int q = tid & 15;
        const float4* row4 = (const float4*)(Msh + (size_t)r * NN + q * 32);
        float m = -3.402823466e38f;
#pragma unroll
        for (int i = 0; i < 8; i++) {
            float4 v = row4[i];
            m = fmaxf(m, fmaxf(fmaxf(v.x, v.y), fmaxf(v.z, v.w)));
        }
        Mmax_sh[r * NCHUNK + q] = m;
    }
    __syncthreads();
    cluster_sync_();   // all CTAs' U/V init + M done before any peer stores arrive

    const uint32_t Ub = smem_u32(U_sh);
    const uint32_t Vb = smem_u32(V_sh);
    const int rowbase = warp * 2;              // 2 rows per warp (CTA-local)
    const int gbase   = rank * RPC + rowbase;  // global sorted row index

    for (int it = 0; it < NITERS; it++) {
        half_step(Msh, U_sh, Mmax_sh, Vb, rowbase, gbase, lane);   // -> V
        cluster_sync_();
        half_step(Msh, V_sh, Mmax_sh, Ub, rowbase, gbase, lane);   // -> U
        cluster_sync_();
    }

    // out[p[a]] = sum_{j<K} 2^( nk2*(t_a - t_j)^2 + U[a] + V[j] )
#pragma unroll
    for (int c = 0; c < 2; c++) {
        const int a = gbase + c;
        const float ta = t_sh[a];
        const float ua = U_sh[a];
        float acc = 0.0f;
        for (int jj = lane; jj < KTOP; jj += 32) {
            float d = ta - t_sh[jj];
            acc += ex2f_(fmaf(d * nk2, d, ua + V_sh[jj]));
        }
#pragma unroll
        for (int o = 16; o > 0; o >>= 1)
            acc += __shfl_xor_sync(0xffffffffu, acc, o);
        if (lane == 0) out[batch * NN + p_sh[a]] = acc;
    }

    // no CTA may exit while peers could still store into its SMEM
    __syncthreads();
    cluster_sync_();
}

extern "C" void kernel_launch(void* const* d_in, const int* in_sizes, int n_in,
                              void* d_out, int out_size) {
    const float* scores = (const float*)d_in[0];
    float* outp = (float*)d_out;
    cudaFuncSetAttribute(sinkhorn_topk_kernel,
                         cudaFuncAttributeMaxDynamicSharedMemorySize,
                         RPC * NN * (int)sizeof(float));
    sinkhorn_topk_kernel<<<NB * CL, NTHREADS, RPC * NN * sizeof(float)>>>(scores, outp);
}

// round 15
// speedup vs baseline: 1.8717x; 1.2365x over previous
#include <cuda_runtime.h>
#include <cstdint>

#define NN       512
#define NB       16
#define KTOP     50
#define NITERS   100
#define NTHREADS 1024   // 32 warps; warp owns 16 rows, 2 lanes per row
#define CUT      30.0f  // element-skip threshold in log2 units

__device__ __forceinline__ float ex2f_(float x) {
    float r; asm("ex2.approx.ftz.f32 %0, %1;" : "=f"(r) : "f"(x)); return r;
}
__device__ __forceinline__ float lg2f_(float x) {
    float r; asm("lg2.approx.f32 %0, %1;" : "=f"(r) : "f"(x)); return r;
}
// order-preserving float <-> u32 total-order mapping
__device__ __forceinline__ uint32_t map_f32(float f) {
    int32_t b = __float_as_int(f);
    return (b >= 0) ? ((uint32_t)b | 0x80000000u) : ~(uint32_t)b;
}
__device__ __forceinline__ float unmap_f32(uint32_t u) {
    int32_t b = (u & 0x80000000u) ? (int32_t)(u & 0x7FFFFFFFu) : (int32_t)~u;
    return __int_as_float(b);
}
__device__ __forceinline__ float warp_max_f32(float x) {
    uint32_t r;
    asm("redux.sync.max.u32 %0, %1, 0xffffffff;" : "=r"(r) : "r"(map_f32(x)));
    return unmap_f32(r);
}
__device__ __forceinline__ float warp_min_f32(float x) {
    uint32_t r;
    asm("redux.sync.min.u32 %0, %1, 0xffffffff;" : "=r"(r) : "r"(map_f32(x)));
    return unmap_f32(r);
}

// Sorted coordinate space: t = sort_desc(s), p: sorted pos -> original idx.
// M[a,b] = nk2*(t_a - t_b)^2 computed on the fly.
//   phase even:  V[a] = -lse2_b( M[a,b] + U[b] )
//   phase odd :  U[a] = -lse2_b( M[a,b] + V[b] )
// Shift = W[a] (diag term => sum >= 1). Element skip: contribute only cols with
// |t_a - t_b| < r, r^2 = (CUT + wm - wa)/k2, wm = max_b W[b]  (skipped elements
// are each < 2^-CUT relative => error ~512*2^-30 per lse).
// out[p[a]] = sum_{j<K} 2^( M[a,j] + U[a] + V[j] )
__global__ void __launch_bounds__(NTHREADS, 1)
sinkhorn_topk_kernel(const float* __restrict__ scores, float* __restrict__ out)
{
    __shared__ __align__(16) float  t_sh[NN];    // sorted descending
    __shared__ __align__(16) float2 TU_sh[NN];   // (t_b, U[b]) interleaved
    __shared__ __align__(16) float2 TV_sh[NN];   // (t_b, V[b]) interleaved
    __shared__ int p_sh[NN];                     // sorted pos -> original index
    __shared__ uint32_t wm_sh[4];                // phase-ring of mapped max(W)

    const int tid   = threadIdx.x;
    const int lane  = tid & 31;
    const int warp  = tid >> 5;
    const int batch = blockIdx.x;
    const float nk2   = -1442.6950408889634f;    // -log2(e)/EPSILON
    const float invk2 =  6.931471805599453e-4f;  // 1/1442.695 = EPSILON*ln2

    if (tid < NN) {
        t_sh[tid] = scores[batch * NN + tid];
        p_sh[tid] = tid;
    }
    if (tid < 4) wm_sh[tid] = 0u;                // 0 = below every mapped float
    __syncthreads();

    // Bitonic sort (value, index) descending — threads 0..511 active
    for (int k = 2; k <= NN; k <<= 1) {
        for (int j = k >> 1; j > 0; j >>= 1) {
            if (tid < NN) {
                int ixj = tid ^ j;
                if (ixj > tid) {
                    float a = t_sh[tid], b = t_sh[ixj];
                    bool desc = ((tid & k) == 0);
                    if (desc ? (a < b) : (a > b)) {
                        t_sh[tid] = b; t_sh[ixj] = a;
                        int pa = p_sh[tid]; p_sh[tid] = p_sh[ixj]; p_sh[ixj] = pa;
                    }
                }
            }
            __syncthreads();
        }
    }

    if (tid < NN) {
        const float tv = t_sh[tid];
        TU_sh[tid] = make_float2(tv, 0.0f);
        TV_sh[tid] = make_float2(tv, 0.0f);
    }
    __syncthreads();

    const int rr = lane >> 1;            // row within warp's 16
    const int h  = lane & 1;             // column-half selector
    const int a  = warp * 16 + rr;       // this lane's sorted row
    const float ta = t_sh[a];

    int lo0 = 0, hi0 = 0, lo1 = 0, hi1 = 0;   // per-step-type windows

    for (int ph = 0; ph < 2 * NITERS; ph++) {
        const int st = ph & 1;
        const float2* __restrict__ S = st ? TV_sh : TU_sh;   // source (t, W)
        float2* __restrict__ D       = st ? TU_sh : TV_sh;   // destination

        const float wm = (ph == 0) ? 0.0f : unmap_f32(wm_sh[(ph - 1) & 3]);
        const float wa = S[a].y;
        const float r  = sqrtf((CUT + wm - wa) * invk2);     // wm >= wa => arg > 0
        const float thi = warp_max_f32(ta + r);              // union over warp rows
        const float tlo = warp_min_f32(ta - r);

        // incremental warp-uniform window [lo, hi): cols with tlo < t[b] < thi
        int lo = st ? lo1 : lo0;
        int hi = st ? hi1 : hi0;
        while (lo > 0  && t_sh[lo - 1] <  thi) lo--;
        while (lo < NN && t_sh[lo]     >= thi) lo++;
        while (hi < NN && t_sh[hi]     >  tlo) hi++;
        while (hi > 0  && t_sh[hi - 1] <= tlo) hi--;
        if (st) { lo1 = lo; hi1 = hi; } else { lo0 = lo; hi0 = hi; }

        const int mid = (lo + hi) >> 1;
        int b        = h ? mid : lo;
        const int be = h ? hi  : mid;

        float s0 = 0.f, s1 = 0.f, s2 = 0.f, s3 = 0.f;
        for (; b + 4 <= be; b += 4) {
            float2 c0 = S[b], c1 = S[b+1], c2 = S[b+2], c3 = S[b+3];
            float d0 = ta - c0.x, d1 = ta - c1.x, d2 = ta - c2.x, d3 = ta - c3.x;
            s0 += ex2f_(fmaf(d0 * nk2, d0, c0.y - wa));
            s1 += ex2f_(fmaf(d1 * nk2, d1, c1.y - wa));
            s2 += ex2f_(fmaf(d2 * nk2, d2, c2.y - wa));
            s3 += ex2f_(fmaf(d3 * nk2, d3, c3.y - wa));
        }
        for (; b < be; b++) {
            float2 c0 = S[b];
            float d0 = ta - c0.x;
            s0 += ex2f_(fmaf(d0 * nk2, d0, c0.y - wa));
        }
        float s = (s0 + s1) + (s2 + s3);
        s += __shfl_xor_sync(0xffffffffu, s, 1);             // combine column halves

        const float v = -(wa + lg2f_(s));
        if (h == 0) D[a].y = v;

        // phase-ring wm update: one redux + one smem atomic per warp
        const float vmax = warp_max_f32(v);
        if (lane == 0) atomicMax(&wm_sh[ph & 3], map_f32(vmax));
        if (tid == 0)  wm_sh[(ph + 2) & 3] = 0u;             // reset 2 phases ahead
        __syncthreads();
    }

    // out[p[a]] = sum_{j<K} 2^( nk2*(t_a - t_j)^2 + U[a] + V[j] )
#pragma unroll 1
    for (int c = 0; c < 16; c++) {
        const int aa = warp * 16 + c;
        const float taa = t_sh[aa];
        const float ua  = TU_sh[aa].y;
        float acc = 0.0f;
        for (int jj = lane; jj < KTOP; jj += 32) {
            float d = taa - t_sh[jj];
            acc += ex2f_(fmaf(d * nk2, d, ua + TV_sh[jj].y));
        }
#pragma unroll
        for (int o = 16; o > 0; o >>= 1)
            acc += __shfl_xor_sync(0xffffffffu, acc, o);
        if (lane == 0) out[batch * NN + p_sh[aa]] = acc;
    }
}

extern "C" void kernel_launch(void* const* d_in, const int* in_sizes, int n_in,
                              void* d_out, int out_size) {
    const float* scores = (const float*)d_in[0];
    float* outp = (float*)d_out;
    sinkhorn_topk_kernel<<<NB, NTHREADS>>>(scores, outp);
}

// round 16
// speedup vs baseline: 2.0498x; 1.0952x over previous
#include <cuda_runtime.h>
#include <cstdint>

#define NN       512
#define NB       16
#define KTOP     50
#define NITERS   100
#define CL       2      // CTAs per cluster (one cluster per batch)
#define RPC      256    // rows per CTA
#define RPW      8      // rows per warp
#define NTHREADS 1024   // 32 warps
#define CUT      26.0f  // element-skip threshold in log2 units

__device__ __forceinline__ uint32_t smem_u32(const void* p) {
    return (uint32_t)__cvta_generic_to_shared(p);
}
__device__ __forceinline__ float ex2f_(float x) {
    float r; asm("ex2.approx.ftz.f32 %0, %1;" : "=f"(r) : "f"(x)); return r;
}
__device__ __forceinline__ float lg2f_(float x) {
    float r; asm("lg2.approx.f32 %0, %1;" : "=f"(r) : "f"(x)); return r;
}
// order-preserving float <-> u32 total-order mapping
__device__ __forceinline__ uint32_t map_f32(float f) {
    int32_t b = __float_as_int(f);
    return (b >= 0) ? ((uint32_t)b | 0x80000000u) : ~(uint32_t)b;
}
__device__ __forceinline__ float unmap_f32(uint32_t u) {
    int32_t b = (u & 0x80000000u) ? (int32_t)(u & 0x7FFFFFFFu) : (int32_t)~u;
    return __int_as_float(b);
}
__device__ __forceinline__ float warp_max_f32(float x) {
    uint32_t r;
    asm("redux.sync.max.u32 %0, %1, 0xffffffff;" : "=r"(r) : "r"(map_f32(x)));
    return unmap_f32(r);
}
__device__ __forceinline__ float warp_min_f32(float x) {
    uint32_t r;
    asm("redux.sync.min.u32 %0, %1, 0xffffffff;" : "=r"(r) : "r"(map_f32(x)));
    return unmap_f32(r);
}
__device__ __forceinline__ void cluster_sync_() {
    asm volatile("barrier.cluster.arrive.aligned;" ::: "memory");
    asm volatile("barrier.cluster.wait.aligned;" ::: "memory");
}
__device__ __forceinline__ uint32_t ctarank_() {
    uint32_t r; asm("mov.u32 %0, %%cluster_ctarank;" : "=r"(r)); return r;
}
__device__ __forceinline__ void st_cluster_f32(uint32_t laddr, uint32_t rank, float v) {
    asm volatile(
        "{\n\t.reg .b32 ra;\n\t"
        "mapa.shared::cluster.u32 ra, %0, %1;\n\t"
        "st.shared::cluster.f32 [ra], %2;\n\t}"
        :: "r"(laddr), "r"(rank), "f"(v) : "memory");
}
__device__ __forceinline__ void red_max_cluster_u32(uint32_t laddr, uint32_t rank, uint32_t v) {
    asm volatile(
        "{\n\t.reg .b32 ra;\n\t"
        "mapa.shared::cluster.u32 ra, %0, %1;\n\t"
        "red.shared::cluster.max.u32 [ra], %2;\n\t}"
        :: "r"(laddr), "r"(rank), "r"(v) : "memory");
}

// Sorted coordinate space: t = sort_desc(s), p: sorted pos -> original idx.
// M[a,b] = nk2*(t_a - t_b)^2 computed on the fly. Two CTAs split rows 256/256.
//   phase even:  V[a] = -lse2_b( M[a,b] + U[b] )
//   phase odd :  U[a] = -lse2_b( M[a,b] + V[b] )
// Shift = W[a]. Element skip: only cols with |t_a - t_b| < r,
// r^2 = (CUT + wm - wa)/k2, wm = max_b W[b] (cluster-wide via red.shared::cluster).
__global__ void __launch_bounds__(NTHREADS, 1) __cluster_dims__(CL, 1, 1)
sinkhorn_topk_kernel(const float* __restrict__ scores, float* __restrict__ out)
{
    __shared__ __align__(16) float  t_sh[NN];    // sorted descending
    __shared__ __align__(16) float2 TU_sh[NN];   // (t_b, U[b]) interleaved
    __shared__ __align__(16) float2 TV_sh[NN];   // (t_b, V[b]) interleaved
    __shared__ int p_sh[NN];                     // sorted pos -> original index
    __shared__ uint32_t wm_sh[4];                // phase-ring of mapped max(W)

    const int tid   = threadIdx.x;
    const int lane  = tid & 31;
    const int warp  = tid >> 5;
    const int rank  = (int)ctarank_();
    const int batch = blockIdx.x / CL;
    const float nk2   = -1442.6950408889634f;    // -log2(e)/EPSILON
    const float invk2 =  6.931471805599453e-4f;  // EPSILON*ln2

    if (tid < NN) {
        t_sh[tid] = scores[batch * NN + tid];
        p_sh[tid] = tid;
    }
    if (tid < 4) wm_sh[tid] = 0u;
    __syncthreads();

    // Bitonic sort (value, index) descending — threads 0..511 (both CTAs duplicate)
    for (int k = 2; k <= NN; k <<= 1) {
        for (int j = k >> 1; j > 0; j >>= 1) {
            if (tid < NN) {
                int ixj = tid ^ j;
                if (ixj > tid) {
                    float a = t_sh[tid], b = t_sh[ixj];
                    bool desc = ((tid & k) == 0);
                    if (desc ? (a < b) : (a > b)) {
                        t_sh[tid] = b; t_sh[ixj] = a;
                        int pa = p_sh[tid]; p_sh[tid] = p_sh[ixj]; p_sh[ixj] = pa;
                    }
                }
            }
            __syncthreads();
        }
    }

    if (tid < NN) {
        const float tv = t_sh[tid];
        TU_sh[tid] = make_float2(tv, 0.0f);
        TV_sh[tid] = make_float2(tv, 0.0f);
    }
    __syncthreads();
    cluster_sync_();   // both CTAs initialized before any DSMEM traffic

    const uint32_t TUb = smem_u32(TU_sh);
    const uint32_t TVb = smem_u32(TV_sh);
    const uint32_t WMb = smem_u32(wm_sh);

    const int rr = lane >> 2;                 // row within warp's 8
    const int h  = lane & 3;                  // quarter-window selector
    const int a  = rank * RPC + warp * RPW + rr;  // this lane's sorted row
    const float ta = t_sh[a];

    int lo0 = 0, hi0 = 0, lo1 = 0, hi1 = 0;   // per-step-type windows

    for (int ph = 0; ph < 2 * NITERS; ph++) {
        const int st = ph & 1;
        const float2* __restrict__ S = st ? TV_sh : TU_sh;   // source (t, W)
        const uint32_t Db            = st ? TUb : TVb;       // destination base

        const float wm = (ph == 0) ? 0.0f : unmap_f32(wm_sh[(ph - 1) & 3]);
        const float wa = S[a].y;
        const float r  = sqrtf((CUT + wm - wa) * invk2);     // wm >= wa => arg > 0
        const float thi = warp_max_f32(ta + r);              // union over warp rows
        const float tlo = warp_min_f32(ta - r);

        // incremental warp-uniform window [lo, hi): cols with tlo < t[b] < thi
        int lo = st ? lo1 : lo0;
        int hi = st ? hi1 : hi0;
        while (lo > 0  && t_sh[lo - 1] <  thi) lo--;
        while (lo < NN && t_sh[lo]     >= thi) lo++;
        while (hi < NN && t_sh[hi]     >  tlo) hi++;
        while (hi > 0  && t_sh[hi - 1] <= tlo) hi--;
        if (st) { lo1 = lo; hi1 = hi; } else { lo0 = lo; hi0 = hi; }

        // quarter split of the window across the row's 4 lanes
        const int qlen = (hi - lo + 3) >> 2;
        int b        = lo + h * qlen;
        int be       = b + qlen;
        if (be > hi) be = hi;
        if (b  > hi) b  = hi;

        float s0 = 0.f, s1 = 0.f, s2 = 0.f, s3 = 0.f;
        for (; b + 4 <= be; b += 4) {
            float2 c0 = S[b], c1 = S[b+1], c2 = S[b+2], c3 = S[b+3];
            float d0 = ta - c0.x, d1 = ta - c1.x, d2 = ta - c2.x, d3 = ta - c3.x;
            s0 += ex2f_(fmaf(d0 * nk2, d0, c0.y - wa));
            s1 += ex2f_(fmaf(d1 * nk2, d1, c1.y - wa));
            s2 += ex2f_(fmaf(d2 * nk2, d2, c2.y - wa));
            s3 += ex2f_(fmaf(d3 * nk2, d3, c3.y - wa));
        }
        for (; b < be; b++) {
            float2 c0 = S[b];
            float d0 = ta - c0.x;
            s0 += ex2f_(fmaf(d0 * nk2, d0, c0.y - wa));
        }
        float s = (s0 + s1) + (s2 + s3);
        s += __shfl_xor_sync(0xffffffffu, s, 1);             // combine quarters
        s += __shfl_xor_sync(0xffffffffu, s, 2);

        const float v = -(wa + lg2f_(s));
        // write this row's new potential into BOTH CTAs (lanes h=0,1 -> ranks 0,1)
        if (h < CL) st_cluster_f32(Db + (uint32_t)a * 8u + 4u, (uint32_t)h, v);

        // cluster-wide running max of new potentials (one red per warp per rank)
        const float vmax = warp_max_f32(v);
        if (lane < CL) red_max_cluster_u32(WMb + ((ph & 3) << 2), (uint32_t)lane, map_f32(vmax));
        if (tid == 0)  wm_sh[(ph + 2) & 3] = 0u;             // reset 2 phases ahead
        cluster_sync_();                                     // potentials + wm visible
    }

    // out[p[a]] = sum_{j<K} 2^( nk2*(t_a - t_j)^2 + U[a] + V[j] )
#pragma unroll 1
    for (int c = 0; c < RPW; c++) {
        const int aa = rank * RPC + warp * RPW + c;
        const float taa = t_sh[aa];
        const float ua  = TU_sh[aa].y;
        float acc = 0.0f;
        for (int jj = lane; jj < KTOP; jj += 32) {
            float d = taa - t_sh[jj];
            acc += ex2f_(fmaf(d * nk2, d, ua + TV_sh[jj].y));
        }
#pragma unroll
        for (int o = 16; o > 0; o >>= 1)
            acc += __shfl_xor_sync(0xffffffffu, acc, o);
        if (lane == 0) out[batch * NN + p_sh[aa]] = acc;
    }
}

extern "C" void kernel_launch(void* const* d_in, const int* in_sizes, int n_in,
                              void* d_out, int out_size) {
    const float* scores = (const float*)d_in[0];
    float* outp = (float*)d_out;
    sinkhorn_topk_kernel<<<NB * CL, NTHREADS>>>(scores, outp);
}

// round 17
// speedup vs baseline: 2.3272x; 1.1353x over previous
#include <cuda_runtime.h>
#include <cstdint>

#define NN       512
#define NB       16
#define KTOP     50
#define NITERS   100
#define CL       4      // CTAs per cluster (one cluster per batch)
#define RPC      128    // rows per CTA
#define RPW      4      // rows per warp
#define NTHREADS 1024   // 32 warps; 8 lanes per row
#define CUT      26.0f  // element-skip threshold in log2 units

__device__ __forceinline__ uint32_t smem_u32(const void* p) {
    return (uint32_t)__cvta_generic_to_shared(p);
}
__device__ __forceinline__ float ex2f_(float x) {
    float r; asm("ex2.approx.ftz.f32 %0, %1;" : "=f"(r) : "f"(x)); return r;
}
__device__ __forceinline__ float lg2f_(float x) {
    float r; asm("lg2.approx.f32 %0, %1;" : "=f"(r) : "f"(x)); return r;
}
// order-preserving float <-> u32 total-order mapping
__device__ __forceinline__ uint32_t map_f32(float f) {
    int32_t b = __float_as_int(f);
    return (b >= 0) ? ((uint32_t)b | 0x80000000u) : ~(uint32_t)b;
}
__device__ __forceinline__ float unmap_f32(uint32_t u) {
    int32_t b = (u & 0x80000000u) ? (int32_t)(u & 0x7FFFFFFFu) : (int32_t)~u;
    return __int_as_float(b);
}
__device__ __forceinline__ float warp_max_f32(float x) {
    uint32_t r;
    asm("redux.sync.max.u32 %0, %1, 0xffffffff;" : "=r"(r) : "r"(map_f32(x)));
    return unmap_f32(r);
}
__device__ __forceinline__ float warp_min_f32(float x) {
    uint32_t r;
    asm("redux.sync.min.u32 %0, %1, 0xffffffff;" : "=r"(r) : "r"(map_f32(x)));
    return unmap_f32(r);
}
__device__ __forceinline__ void cluster_sync_() {
    asm volatile("barrier.cluster.arrive.aligned;" ::: "memory");
    asm volatile("barrier.cluster.wait.aligned;" ::: "memory");
}
__device__ __forceinline__ uint32_t ctarank_() {
    uint32_t r; asm("mov.u32 %0, %%cluster_ctarank;" : "=r"(r)); return r;
}
__device__ __forceinline__ void st_cluster_f32(uint32_t laddr, uint32_t rank, float v) {
    asm volatile(
        "{\n\t.reg .b32 ra;\n\t"
        "mapa.shared::cluster.u32 ra, %0, %1;\n\t"
        "st.shared::cluster.f32 [ra], %2;\n\t}"
        :: "r"(laddr), "r"(rank), "f"(v) : "memory");
}
__device__ __forceinline__ void red_max_cluster_u32(uint32_t laddr, uint32_t rank, uint32_t v) {
    asm volatile(
        "{\n\t.reg .b32 ra;\n\t"
        "mapa.shared::cluster.u32 ra, %0, %1;\n\t"
        "red.shared::cluster.max.u32 [ra], %2;\n\t}"
        :: "r"(laddr), "r"(rank), "r"(v) : "memory");
}

// Sorted, pre-scaled coordinate space: t' = sqrt(k2) * sort_desc(s), so the cost
// exponent is x = -(t'a - t'b)^2 + W[b]  (no shift: |W| bounded well inside fp32
// exponent range; lse precision is set by the max term either way).
//   phase even:  V[a] = -lg2 sum_b 2^( -(d')^2 + U[b] )
//   phase odd :  U[a] = -lg2 sum_b 2^( -(d')^2 + V[b] )
// Element skip: only cols with (d')^2 < CUT + wm - wa  (wm = max_b W[b],
// cluster-wide via red.shared::cluster ring). Four CTAs split rows 128 each.
__global__ void __launch_bounds__(NTHREADS, 1) __cluster_dims__(CL, 1, 1)
sinkhorn_topk_kernel(const float* __restrict__ scores, float* __restrict__ out)
{
    __shared__ __align__(16) float  t_sh[NN];    // t' sorted descending
    __shared__ __align__(16) float2 TU_sh[NN];   // (t'_b, U[b]) interleaved
    __shared__ __align__(16) float2 TV_sh[NN];   // (t'_b, V[b]) interleaved
    __shared__ int p_sh[NN];                     // sorted pos -> original index
    __shared__ uint32_t wm_sh[4];                // phase-ring of mapped max(W)

    const int tid   = threadIdx.x;
    const int lane  = tid & 31;
    const int warp  = tid >> 5;
    const int rank  = (int)ctarank_();
    const int batch = blockIdx.x / CL;
    const float sqk2 = 37.982825f;               // sqrt(log2(e)/EPSILON)

    if (tid < NN) {
        t_sh[tid] = scores[batch * NN + tid];
        p_sh[tid] = tid;
    }
    if (tid < 4) wm_sh[tid] = 0u;
    __syncthreads();

    // Bitonic sort (value, index) descending — threads 0..511 (CTAs duplicate)
    for (int k = 2; k <= NN; k <<= 1) {
        for (int j = k >> 1; j > 0; j >>= 1) {
            if (tid < NN) {
                int ixj = tid ^ j;
                if (ixj > tid) {
                    float a = t_sh[tid], b = t_sh[ixj];
                    bool desc = ((tid & k) == 0);
                    if (desc ? (a < b) : (a > b)) {
                        t_sh[tid] = b; t_sh[ixj] = a;
                        int pa = p_sh[tid]; p_sh[tid] = p_sh[ixj]; p_sh[ixj] = pa;
                    }
                }
            }
            __syncthreads();
        }
    }

    // pre-scale to t' and build interleaved source arrays
    if (tid < NN) {
        const float tp = t_sh[tid] * sqk2;
        t_sh[tid] = tp;
        TU_sh[tid] = make_float2(tp, 0.0f);
        TV_sh[tid] = make_float2(tp, 0.0f);
    }
    __syncthreads();
    cluster_sync_();   // all CTAs initialized before any DSMEM traffic

    const uint32_t TUb = smem_u32(TU_sh);
    const uint32_t TVb = smem_u32(TV_sh);
    const uint32_t WMb = smem_u32(wm_sh);

    const int rr = lane >> 3;                     // row within warp's 4
    const int h  = lane & 7;                      // stride-8 slot within the row
    const int a  = rank * RPC + warp * RPW + rr;  // this lane's sorted row
    const float ta = t_sh[a];

    int lo0 = 0, hi0 = 0, lo1 = 0, hi1 = 0;       // per-step-type windows

    for (int ph = 0; ph < 2 * NITERS; ph++) {
        const int st = ph & 1;
        const float2* __restrict__ S = st ? TV_sh : TU_sh;   // source (t', W)
        const uint32_t Db            = st ? TUb : TVb;       // destination base

        const float wm = (ph == 0) ? 0.0f : unmap_f32(wm_sh[(ph - 1) & 3]);
        const float wa = S[a].y;
        const float r  = sqrtf(CUT + wm - wa);               // wm >= wa => arg > 0
        const float thi = warp_max_f32(ta + r);              // union over warp rows
        const float tlo = warp_min_f32(ta - r);

        // incremental warp-uniform window [lo, hi): cols with tlo < t'[b] < thi
        int lo = st ? lo1 : lo0;
        int hi = st ? hi1 : hi0;
        while (lo > 0  && t_sh[lo - 1] <  thi) lo--;
        while (lo < NN && t_sh[lo]     >= thi) lo++;
        while (hi < NN && t_sh[hi]     >  tlo) hi++;
        while (hi > 0  && t_sh[hi - 1] <= tlo) hi--;
        if (st) { lo1 = lo; hi1 = hi; } else { lo0 = lo; hi0 = hi; }

        // lanes of a row stride 8 through the window (coalesced, conflict-free)
        int b = lo + h;
        float s0 = 0.f, s1 = 0.f, s2 = 0.f, s3 = 0.f;
        for (; b + 24 < hi; b += 32) {
            float2 c0 = S[b], c1 = S[b+8], c2 = S[b+16], c3 = S[b+24];
            float d0 = ta - c0.x, d1 = ta - c1.x, d2 = ta - c2.x, d3 = ta - c3.x;
            s0 += ex2f_(fmaf(d0, -d0, c0.y));
            s1 += ex2f_(fmaf(d1, -d1, c1.y));
            s2 += ex2f_(fmaf(d2, -d2, c2.y));
            s3 += ex2f_(fmaf(d3, -d3, c3.y));
        }
        for (; b < hi; b += 8) {
            float2 c0 = S[b];
            float d0 = ta - c0.x;
            s0 += ex2f_(fmaf(d0, -d0, c0.y));
        }
        float s = (s0 + s1) + (s2 + s3);
        s += __shfl_xor_sync(0xffffffffu, s, 1);             // combine 8 slots
        s += __shfl_xor_sync(0xffffffffu, s, 2);
        s += __shfl_xor_sync(0xffffffffu, s, 4);

        const float v = -lg2f_(s);
        // write this row's new potential into all CL CTAs (lanes h<CL -> ranks)
        if (h < CL) st_cluster_f32(Db + (uint32_t)a * 8u + 4u, (uint32_t)h, v);

        // cluster-wide running max of new potentials
        const float vmax = warp_max_f32(v);
        if (lane < CL) red_max_cluster_u32(WMb + ((ph & 3) << 2), (uint32_t)lane, map_f32(vmax));
        if (tid == 0)  wm_sh[(ph + 2) & 3] = 0u;             // reset 2 phases ahead
        cluster_sync_();                                     // potentials + wm visible
    }

    // out[p[a]] = sum_{j<K} 2^( -(t'a - t'j)^2 + U[a] + V[j] )
#pragma unroll 1
    for (int c = 0; c < RPW; c++) {
        const int aa = rank * RPC + warp * RPW + c;
        const float taa = t_sh[aa];
        const float ua  = TU_sh[aa].y;
        float acc = 0.0f;
        for (int jj = lane; jj < KTOP; jj += 32) {
            float d = taa - t_sh[jj];
            acc += ex2f_(fmaf(d, -d, ua + TV_sh[jj].y));
        }
#pragma unroll
        for (int o = 16; o > 0; o >>= 1)
            acc += __shfl_xor_sync(0xffffffffu, acc, o);
        if (lane == 0) out[batch * NN + p_sh[aa]] = acc;
    }
}

extern "C" void kernel_launch(void* const* d_in, const int* in_sizes, int n_in,
                              void* d_out, int out_size) {
    const float* scores = (const float*)d_in[0];
    float* outp = (float*)d_out;
    sinkhorn_topk_kernel<<<NB * CL, NTHREADS>>>(scores, outp);
}